// round 7
// baseline (speedup 1.0000x reference)
#include <cuda_runtime.h>
#include <cuda_fp16.h>

#define NN   50000
#define NE   800000
#define NB   4
#define IND  64
#define HIDD 64
#define OUTD 32
#define NROWS (NN * NB)          // 200000

typedef unsigned long long u64;

// ---------------- scratch (static device globals; zero-init at load) ----------------
__device__ __align__(16) __half g_z1[(size_t)NN * NB * HIDD];  // fp16 (h@W1)*snorm, node-major [q=n*4+b][64]
__device__ __align__(16) float  g_agg1[(size_t)NN * NB * HIDD];
__device__ __align__(16) __half g_z2[(size_t)NN * NB * OUTD];  // fp16 snorm*(relu(agg*dn+b1)@W2)
__device__ float g_snorm[NN];
__device__ float g_dnorm[NN];
__device__ int   g_odeg[NN];     // zeroed at tail of k_agg2 each call (zero-init at load)
__device__ int   g_ideg[NN];     // ditto
__device__ int   g_coff[NN];
__device__ int   g_cur [NN];
__device__ int   g_esrc[NE];
__device__ volatile u64 g_pub[128];   // scan block publications: bit63=ready | total

// ---------------- f32x2 packed-FMA helpers (Blackwell FFMA2) ----------------
__device__ __forceinline__ u64 pack2(float x, float y) {
    u64 r; asm("mov.b64 %0, {%1,%2};" : "=l"(r) : "f"(x), "f"(y)); return r;
}
__device__ __forceinline__ void ffma2(u64& d, u64 a, u64 b) {
    asm("fma.rn.f32x2 %0, %1, %2, %0;" : "+l"(d) : "l"(a), "l"(b));
}
__device__ __forceinline__ float2 unpack2(u64 v) {
    float2 f; asm("mov.b64 {%0,%1}, %2;" : "=f"(f.x), "=f"(f.y) : "l"(v)); return f;
}

// ---------------- degree count (+ reset scan publications for this call) ----------------
__global__ void k_deg(const int* __restrict__ src, const int* __restrict__ dst) {
    int i = blockIdx.x * blockDim.x + threadIdx.x;
    if (blockIdx.x == 0 && threadIdx.x < 128) g_pub[threadIdx.x] = 0ull;
    int stride = gridDim.x * blockDim.x;
    for (int e = i; e < NE; e += stride) {
        atomicAdd(&g_odeg[__ldg(src + e)], 1);
        atomicAdd(&g_ideg[__ldg(dst + e)], 1);
    }
}

// ---------------- single-pass scan + norms (scan1+scan2+scan3 fused) ----------------
#define SCAN_BLK 512
#define N_SCAN_BLKS ((NN + SCAN_BLK - 1) / SCAN_BLK)   // 98

__global__ void __launch_bounds__(SCAN_BLK) k_scanall() {
    __shared__ int ws[16];
    __shared__ int s_base;
    int t = threadIdx.x;
    int bid = blockIdx.x;
    int g = bid * SCAN_BLK + t;
    int ideg = (g < NN) ? g_ideg[g] : 0;

    // block-wide inclusive scan (warp shuffles)
    int x = ideg;
    #pragma unroll
    for (int o = 1; o < 32; o <<= 1) {
        int y = __shfl_up_sync(0xffffffffu, x, o);
        if ((t & 31) >= o) x += y;
    }
    if ((t & 31) == 31) ws[t >> 5] = x;
    __syncthreads();
    if (t < 32) {
        int s = (t < 16) ? ws[t] : 0;
        #pragma unroll
        for (int o = 1; o < 16; o <<= 1) {
            int y = __shfl_up_sync(0xffffffffu, s, o);
            if (t >= o) s += y;
        }
        if (t < 16) ws[t] = s;
    }
    __syncthreads();
    int wbase = (t >> 5) ? ws[(t >> 5) - 1] : 0;
    int incl = x + wbase;                      // inclusive within block

    // publish this block's total (single 64-bit word: ready bit + value)
    if (t == SCAN_BLK - 1)
        g_pub[bid] = (1ull << 63) | (u64)(unsigned)incl;

    // one warp gathers predecessors' totals
    if (t < 32) {
        int sum = 0;
        for (int j = t; j < bid; j += 32) {
            u64 p;
            do { p = g_pub[j]; } while (!(p >> 63));
            sum += (int)(unsigned)p;
        }
        #pragma unroll
        for (int o = 16; o > 0; o >>= 1)
            sum += __shfl_xor_sync(0xffffffffu, sum, o);
        if (t == 0) s_base = sum;
    }
    __syncthreads();

    if (g < NN) {
        int ex = s_base + incl - ideg;         // global exclusive prefix
        g_coff[g] = ex;
        g_cur[g]  = ex;
        g_snorm[g] = rsqrtf((float)max(g_odeg[g], 1));
        g_dnorm[g] = rsqrtf((float)max(ideg, 1));
    }
}

__global__ void k_fill(const int* __restrict__ src, const int* __restrict__ dst) {
    int i = blockIdx.x * blockDim.x + threadIdx.x;
    int stride = gridDim.x * blockDim.x;
    for (int e = i; e < NE; e += stride) {
        int d = __ldg(dst + e);
        int pos = atomicAdd(&g_cur[d], 1);
        g_esrc[pos] = __ldg(src + e);
    }
}

// ---------------- GEMM 1: z1[q=n*4+b] = half( snorm[n] * (h[r=b*NN+n] @ W1) ) ----------------
__global__ void __launch_bounds__(256) k_gemm1(const float* __restrict__ h,
                                               const float* __restrict__ W1) {
    __shared__ float sA[IND][128];   // transposed + XOR-swizzled
    __shared__ float sB[IND * HIDD];
    int tid = threadIdx.x;
    int lane = tid & 31;
    int cgrp = tid >> 5;
    int c0 = cgrp * 8;
    int row0 = blockIdx.x * 128;

    #pragma unroll
    for (int i = tid; i < IND * HIDD; i += 256) sB[i] = __ldg(W1 + i);
    #pragma unroll
    for (int it = 0; it < 8; it++) {
        int idx = tid + it * 256;
        int r_l = idx >> 4;
        int kq  = idx & 15;
        int row = row0 + r_l;
        float4 v = make_float4(0.f, 0.f, 0.f, 0.f);
        if (row < NROWS) v = __ldg((const float4*)(h + (size_t)row * IND + kq * 4));
        int col = r_l ^ kq;
        sA[kq * 4 + 0][col] = v.x;
        sA[kq * 4 + 1][col] = v.y;
        sA[kq * 4 + 2][col] = v.z;
        sA[kq * 4 + 3][col] = v.w;
    }
    __syncthreads();

    u64 acc[4][4];
    #pragma unroll
    for (int r = 0; r < 4; r++)
        #pragma unroll
        for (int c = 0; c < 4; c++) acc[r][c] = 0ull;

    #pragma unroll 4
    for (int k = 0; k < IND; k++) {
        int s = (k >> 2) & 15;
        u64 ap[4];
        #pragma unroll
        for (int r = 0; r < 4; r++) {
            float a = sA[k][(lane + 32 * r) ^ s];
            ap[r] = pack2(a, a);
        }
        ulonglong2 b01 = *(const ulonglong2*)&sB[k * HIDD + c0];
        ulonglong2 b23 = *(const ulonglong2*)&sB[k * HIDD + c0 + 4];
        u64 bp[4] = {b01.x, b01.y, b23.x, b23.y};
        #pragma unroll
        for (int r = 0; r < 4; r++)
            #pragma unroll
            for (int c = 0; c < 4; c++) ffma2(acc[r][c], ap[r], bp[c]);
    }

    #pragma unroll
    for (int r = 0; r < 4; r++) {
        int row = row0 + lane + 32 * r;
        if (row >= NROWS) continue;
        int b = row / NN, n = row - b * NN;
        float sc = g_snorm[n];
        int q = n * NB + b;
        float2 p0 = unpack2(acc[r][0]), p1 = unpack2(acc[r][1]);
        float2 p2 = unpack2(acc[r][2]), p3 = unpack2(acc[r][3]);
        __half2 h0 = __floats2half2_rn(sc * p0.x, sc * p0.y);
        __half2 h1 = __floats2half2_rn(sc * p1.x, sc * p1.y);
        __half2 h2 = __floats2half2_rn(sc * p2.x, sc * p2.y);
        __half2 h3 = __floats2half2_rn(sc * p3.x, sc * p3.y);
        uint4 st;
        st.x = *(unsigned*)&h0; st.y = *(unsigned*)&h1;
        st.z = *(unsigned*)&h2; st.w = *(unsigned*)&h3;
        *(uint4*)(g_z1 + (size_t)q * HIDD + c0) = st;   // 16B aligned
    }
}

// ---------------- gather layer 1: agg1[n] = sum z1[src]  (fp16 in, fp32 acc/out) ----------------
__global__ void __launch_bounds__(256) k_agg1() {
    int lane = threadIdx.x & 31;
    int n = blockIdx.x * 8 + (threadIdx.x >> 5);
    if (n >= NN) return;
    int beg = g_coff[n];
    int deg = g_ideg[n];
    float2 a[4];
    #pragma unroll
    for (int j = 0; j < 4; j++) a[j] = make_float2(0.f, 0.f);

    int i = 0;
    for (; i + 3 < deg; i += 4) {
        int s0 = __ldg(g_esrc + beg + i);
        int s1 = __ldg(g_esrc + beg + i + 1);
        int s2 = __ldg(g_esrc + beg + i + 2);
        int s3 = __ldg(g_esrc + beg + i + 3);
        uint4 v0 = __ldg((const uint4*)(g_z1 + (size_t)s0 * (NB * HIDD)) + lane);
        uint4 v1 = __ldg((const uint4*)(g_z1 + (size_t)s1 * (NB * HIDD)) + lane);
        uint4 v2 = __ldg((const uint4*)(g_z1 + (size_t)s2 * (NB * HIDD)) + lane);
        uint4 v3 = __ldg((const uint4*)(g_z1 + (size_t)s3 * (NB * HIDD)) + lane);
        const unsigned* w0 = &v0.x;
        const unsigned* w1 = &v1.x;
        const unsigned* w2 = &v2.x;
        const unsigned* w3 = &v3.x;
        #pragma unroll
        for (int j = 0; j < 4; j++) {
            float2 f0 = __half22float2(*(const __half2*)&w0[j]);
            float2 f1 = __half22float2(*(const __half2*)&w1[j]);
            float2 f2 = __half22float2(*(const __half2*)&w2[j]);
            float2 f3 = __half22float2(*(const __half2*)&w3[j]);
            a[j].x += (f0.x + f1.x) + (f2.x + f3.x);
            a[j].y += (f0.y + f1.y) + (f2.y + f3.y);
        }
    }
    for (; i < deg; i++) {
        int s0 = __ldg(g_esrc + beg + i);
        uint4 v0 = __ldg((const uint4*)(g_z1 + (size_t)s0 * (NB * HIDD)) + lane);
        const unsigned* w0 = &v0.x;
        #pragma unroll
        for (int j = 0; j < 4; j++) {
            float2 f0 = __half22float2(*(const __half2*)&w0[j]);
            a[j].x += f0.x;
            a[j].y += f0.y;
        }
    }
    float* ap = g_agg1 + (size_t)n * (NB * HIDD) + lane * 8;
    *(float4*)(ap)     = make_float4(a[0].x, a[0].y, a[1].x, a[1].y);
    *(float4*)(ap + 4) = make_float4(a[2].x, a[2].y, a[3].x, a[3].y);
}

// ---------------- GEMM 2: z2[q] = half( snorm * (relu(agg1*dnorm + b1) @ W2) ) ----------------
__global__ void __launch_bounds__(256) k_gemm2(const float* __restrict__ W2,
                                               const float* __restrict__ b1) {
    __shared__ float sA[HIDD][128];
    __shared__ float sB[HIDD * OUTD];
    int tid = threadIdx.x;
    int lane = tid & 31;
    int cgrp = tid >> 5;
    int c0 = cgrp * 4;
    int row0 = blockIdx.x * 128;

    #pragma unroll
    for (int i = tid; i < HIDD * OUTD; i += 256) sB[i] = __ldg(W2 + i);
    #pragma unroll
    for (int it = 0; it < 8; it++) {
        int idx = tid + it * 256;
        int r_l = idx >> 4;
        int kq  = idx & 15;
        int row = row0 + r_l;
        float4 v = make_float4(0.f, 0.f, 0.f, 0.f);
        if (row < NROWS) {
            float dn = g_dnorm[row >> 2];
            float4 a = *(const float4*)(g_agg1 + (size_t)row * HIDD + kq * 4);
            const float4 bb = __ldg((const float4*)(b1 + kq * 4));
            v.x = fmaxf(a.x * dn + bb.x, 0.f);
            v.y = fmaxf(a.y * dn + bb.y, 0.f);
            v.z = fmaxf(a.z * dn + bb.z, 0.f);
            v.w = fmaxf(a.w * dn + bb.w, 0.f);
        }
        int col = r_l ^ kq;
        sA[kq * 4 + 0][col] = v.x;
        sA[kq * 4 + 1][col] = v.y;
        sA[kq * 4 + 2][col] = v.z;
        sA[kq * 4 + 3][col] = v.w;
    }
    __syncthreads();

    u64 acc[4][2];
    #pragma unroll
    for (int r = 0; r < 4; r++) { acc[r][0] = 0ull; acc[r][1] = 0ull; }

    #pragma unroll 4
    for (int k = 0; k < HIDD; k++) {
        int s = (k >> 2) & 15;
        u64 ap[4];
        #pragma unroll
        for (int r = 0; r < 4; r++) {
            float a = sA[k][(lane + 32 * r) ^ s];
            ap[r] = pack2(a, a);
        }
        ulonglong2 b01 = *(const ulonglong2*)&sB[k * OUTD + c0];
        #pragma unroll
        for (int r = 0; r < 4; r++) {
            ffma2(acc[r][0], ap[r], b01.x);
            ffma2(acc[r][1], ap[r], b01.y);
        }
    }

    #pragma unroll
    for (int r = 0; r < 4; r++) {
        int row = row0 + lane + 32 * r;
        if (row >= NROWS) continue;
        float sc = g_snorm[row >> 2];
        float2 p0 = unpack2(acc[r][0]), p1 = unpack2(acc[r][1]);
        __half2 h0 = __floats2half2_rn(sc * p0.x, sc * p0.y);
        __half2 h1 = __floats2half2_rn(sc * p1.x, sc * p1.y);
        uint2 st;
        st.x = *(unsigned*)&h0; st.y = *(unsigned*)&h1;
        *(uint2*)(g_z2 + (size_t)row * OUTD + c0) = st;   // 8B aligned
    }
}

// ---------------- gather layer 2 + epilogue -> out[b][n][f]  (+ degree re-zero) ----------------
__global__ void __launch_bounds__(256) k_agg2(const float* __restrict__ b2,
                                              float* __restrict__ out) {
    int lane = threadIdx.x & 31;
    int n = blockIdx.x * 8 + (threadIdx.x >> 5);
    if (n >= NN) return;
    int beg = g_coff[n];
    int deg = g_ideg[n];
    float2 a0 = make_float2(0.f, 0.f), a1 = a0;

    int i = 0;
    for (; i + 3 < deg; i += 4) {
        int s0 = __ldg(g_esrc + beg + i);
        int s1 = __ldg(g_esrc + beg + i + 1);
        int s2 = __ldg(g_esrc + beg + i + 2);
        int s3 = __ldg(g_esrc + beg + i + 3);
        uint2 v0 = __ldg((const uint2*)(g_z2 + (size_t)s0 * (NB * OUTD)) + lane);
        uint2 v1 = __ldg((const uint2*)(g_z2 + (size_t)s1 * (NB * OUTD)) + lane);
        uint2 v2 = __ldg((const uint2*)(g_z2 + (size_t)s2 * (NB * OUTD)) + lane);
        uint2 v3 = __ldg((const uint2*)(g_z2 + (size_t)s3 * (NB * OUTD)) + lane);
        float2 f;
        f = __half22float2(*(const __half2*)&v0.x); a0.x += f.x; a0.y += f.y;
        f = __half22float2(*(const __half2*)&v0.y); a1.x += f.x; a1.y += f.y;
        f = __half22float2(*(const __half2*)&v1.x); a0.x += f.x; a0.y += f.y;
        f = __half22float2(*(const __half2*)&v1.y); a1.x += f.x; a1.y += f.y;
        f = __half22float2(*(const __half2*)&v2.x); a0.x += f.x; a0.y += f.y;
        f = __half22float2(*(const __half2*)&v2.y); a1.x += f.x; a1.y += f.y;
        f = __half22float2(*(const __half2*)&v3.x); a0.x += f.x; a0.y += f.y;
        f = __half22float2(*(const __half2*)&v3.y); a1.x += f.x; a1.y += f.y;
    }
    for (; i < deg; i++) {
        int s0 = __ldg(g_esrc + beg + i);
        uint2 v0 = __ldg((const uint2*)(g_z2 + (size_t)s0 * (NB * OUTD)) + lane);
        float2 f;
        f = __half22float2(*(const __half2*)&v0.x); a0.x += f.x; a0.y += f.y;
        f = __half22float2(*(const __half2*)&v0.y); a1.x += f.x; a1.y += f.y;
    }

    float dn = g_dnorm[n];
    int b = lane >> 3, fq = lane & 7;
    float4 bb = __ldg((const float4*)(b2 + fq * 4));
    float4 o = make_float4(a0.x * dn + bb.x, a0.y * dn + bb.y,
                           a1.x * dn + bb.z, a1.y * dn + bb.w);
    *(float4*)(out + ((size_t)b * NN + n) * OUTD + fq * 4) = o;

    // restore invariant for the next call (this warp is the sole owner of node n)
    if (lane == 0) { g_odeg[n] = 0; g_ideg[n] = 0; }
}

// ---------------- launch ----------------

extern "C" void kernel_launch(void* const* d_in, const int* in_sizes, int n_in,
                              void* d_out, int out_size) {
    const float* h  = (const float*)d_in[0];
    const float* W1 = (const float*)d_in[1];
    const float* b1 = (const float*)d_in[2];
    const float* W2 = (const float*)d_in[3];
    const float* b2 = (const float*)d_in[4];
    const int* src  = (const int*)d_in[5];
    const int* dst  = (const int*)d_in[6];
    float* out = (float*)d_out;

    k_deg<<<2048, 256>>>(src, dst);
    k_scanall<<<N_SCAN_BLKS, SCAN_BLK>>>();
    k_fill<<<2048, 256>>>(src, dst);
    k_gemm1<<<(NROWS + 127) / 128, 256>>>(h, W1);
    k_agg1<<<(NN + 7) / 8, 256>>>();
    k_gemm2<<<(NROWS + 127) / 128, 256>>>(W2, b1);
    k_agg2<<<(NN + 7) / 8, 256>>>(b2, out);
}